// round 4
// baseline (speedup 1.0000x reference)
#include <cuda_runtime.h>

#define NPTS 4096
#define CCH  128
#define GG   49
#define PAD  132        // corr smem row stride (floats)
#define MROWS 16384     // 4 levels * 4096 points
#define XSTRIDE 2432    // padded K (76*32); cols [2401,2432) stay zero (.bss)

// ---- scratch (static device globals: allocation-free, zero-initialized) ----
__device__ float    g_fmapt[2088960];                  // fmaps transposed to [H,W,C]
__device__ unsigned g_Xhi[(size_t)MROWS * XSTRIDE];    // tf32 hi of corr volumes
__device__ unsigned g_Xlo[(size_t)MROWS * XSTRIDE];    // tf32 lo residual
__device__ unsigned g_Whi[(size_t)XSTRIDE * 384];      // tf32 hi of w1 (pad rows zero)
__device__ unsigned g_Wlo[(size_t)XSTRIDE * 384];
__device__ float    g_H[(size_t)MROWS * 384];          // MLP1 activations

// ---- tf32 helpers ----
__device__ __forceinline__ unsigned f2tf32(float x) {
  unsigned r; asm("cvt.rna.tf32.f32 %0, %1;" : "=r"(r) : "f"(x)); return r;
}
__device__ __forceinline__ void mma_tf32(float& d0, float& d1, float& d2, float& d3,
                                         unsigned a0, unsigned a1, unsigned a2, unsigned a3,
                                         unsigned b0, unsigned b1) {
  asm volatile("mma.sync.aligned.m16n8k8.row.col.f32.tf32.tf32.f32 "
               "{%0,%1,%2,%3}, {%4,%5,%6,%7}, {%8,%9}, {%0,%1,%2,%3};"
               : "+f"(d0), "+f"(d1), "+f"(d2), "+f"(d3)
               : "r"(a0), "r"(a1), "r"(a2), "r"(a3), "r"(b0), "r"(b1));
}

// ---- cp.async helpers ----
__device__ __forceinline__ void cpasync16(unsigned dst_smem, const void* src) {
  asm volatile("cp.async.cg.shared.global [%0], [%1], 16;" :: "r"(dst_smem), "l"(src));
}
__device__ __forceinline__ void cp_commit() { asm volatile("cp.async.commit_group;"); }
template <int NN> __device__ __forceinline__ void cp_wait() {
  asm volatile("cp.async.wait_group %0;" :: "n"(NN));
}

// ============================================================
// Kernel 0: transpose fmap [C,H,W] -> [H,W,C]
// ============================================================
__global__ void k_transpose(const float* __restrict__ in, int HW, int outOff) {
  int p = blockIdx.x;
  int c = threadIdx.x;
  g_fmapt[(size_t)outOff + (size_t)p * CCH + c] = in[(size_t)c * HW + p];
}

// Kernel 0b: pre-split w1 into tf32 hi/lo (one pass per call; layout [k][n])
__global__ void k_wsplit(const float* __restrict__ w1) {
  int i = blockIdx.x * blockDim.x + threadIdx.x;
  if (i >= 2401 * 384) return;
  float v = w1[i];
  unsigned hi = f2tf32(v);
  g_Whi[i] = hi;
  g_Wlo[i] = f2tf32(v - __uint_as_float(hi));
}

// ============================================================
// Kernel 1: per (level, point): bilinear 7x7xC gather + 49x49x128 corr GEMM
// epilogue emits tf32 hi/lo split of X directly.
// ============================================================
__global__ __launch_bounds__(256) void k_corr(
    const float* __restrict__ tfeat,   // [49, N, 128]
    const float* __restrict__ coords,  // [N, 2]
    int H, int W, int fmOff, int level, float scale)
{
  extern __shared__ float sm[];
  float* tmpl_s = sm;                // [49][PAD]
  float* cf_s   = sm + GG * PAD;     // [49][PAD]
  const float* fmap = g_fmapt + fmOff;   // [H,W,C]
  const int n = blockIdx.x;
  const int tid = threadIdx.x;

  for (int idx = tid; idx < GG * CCH; idx += 256) {
    int t = idx >> 7, c = idx & 127;
    tmpl_s[t * PAD + c] = tfeat[(size_t)t * (NPTS * CCH) + (size_t)n * CCH + c];
  }

  float cx = coords[2 * n]     * scale;
  float cy = coords[2 * n + 1] * scale;

  {
    int c    = tid & 127;
    int half = tid >> 7;
    for (int p = half; p < GG; p += 2) {
      int gi = p / 7, gj = p - gi * 7;
      float xs = cx + (float)(gi - 3);
      float ys = cy + (float)(gj - 3);
      float x0f = floorf(xs), y0f = floorf(ys);
      float wx = xs - x0f, wy = ys - y0f;
      int x0 = (int)x0f, y0 = (int)y0f;
      float w00 = (1.f - wy) * (1.f - wx);
      float w01 = (1.f - wy) * wx;
      float w10 = wy * (1.f - wx);
      float w11 = wy * wx;
      float v = 0.f;
      bool xin0 = (x0 >= 0) && (x0 < W);
      bool xin1 = (x0 + 1 >= 0) && (x0 + 1 < W);
      if (y0 >= 0 && y0 < H) {
        size_t rb = (size_t)y0 * W;
        if (xin0) v += w00 * fmap[(rb + x0) * CCH + c];
        if (xin1) v += w01 * fmap[(rb + x0 + 1) * CCH + c];
      }
      if (y0 + 1 >= 0 && y0 + 1 < H) {
        size_t rb = (size_t)(y0 + 1) * W;
        if (xin0) v += w10 * fmap[(rb + x0) * CCH + c];
        if (xin1) v += w11 * fmap[(rb + x0 + 1) * CCH + c];
      }
      cf_s[p * PAD + c] = v;
    }
  }
  __syncthreads();

  int tx = tid & 15, ty = tid >> 4;
  float acc[4][4];
#pragma unroll
  for (int a = 0; a < 4; a++)
#pragma unroll
    for (int b = 0; b < 4; b++) acc[a][b] = 0.f;

  int hw[4], ij[4];
#pragma unroll
  for (int a = 0; a < 4; a++) {
    int h = ty + 16 * a; hw[a] = (h > 48) ? 48 : h;
    int j = tx + 16 * a; ij[a] = (j > 48) ? 48 : j;
  }

#pragma unroll 4
  for (int cc = 0; cc < CCH; cc += 4) {
    float4 av[4], bv[4];
#pragma unroll
    for (int a = 0; a < 4; a++) av[a] = *(const float4*)&cf_s[hw[a] * PAD + cc];
#pragma unroll
    for (int b = 0; b < 4; b++) bv[b] = *(const float4*)&tmpl_s[ij[b] * PAD + cc];
#pragma unroll
    for (int a = 0; a < 4; a++)
#pragma unroll
      for (int b = 0; b < 4; b++) {
        acc[a][b] += av[a].x * bv[b].x;
        acc[a][b] += av[a].y * bv[b].y;
        acc[a][b] += av[a].z * bv[b].z;
        acc[a][b] += av[a].w * bv[b].w;
      }
  }

  size_t rowbase = ((size_t)level * NPTS + n) * XSTRIDE;
#pragma unroll
  for (int a = 0; a < 4; a++)
#pragma unroll
    for (int b = 0; b < 4; b++)
      if ((ty + 16 * a) < GG && (tx + 16 * b) < GG) {
        float v = acc[a][b];
        unsigned hi = f2tf32(v);
        size_t o = rowbase + (size_t)hw[a] * GG + ij[b];
        g_Xhi[o] = hi;
        g_Xlo[o] = f2tf32(v - __uint_as_float(hi));
      }
}

// ============================================================
// Kernel 2: H = gelu_exact(X @ w1 + b1) via 3xTF32 mma.sync
// M=16384 K=2432 N=384. BM=128 BN=128 BK=32, 256 thr (8 warps),
// warp tile 32x64. cp.async double-buffered; pre-split tf32 inputs.
// smem/stage: Ah,Al [128][36] + Bh,Bl [32][136] = 71680 B; x2 stages.
// ============================================================
#define MBM 128
#define MBN 128
#define MBK 32
#define ASTR 36
#define BSTR 136
#define STAGE_WORDS (2 * MBM * ASTR + 2 * MBK * BSTR)   // 17920

__global__ __launch_bounds__(256) void k_mlp1(const float* __restrict__ bias) {
  extern __shared__ unsigned smu[];
  const int tid  = threadIdx.x;
  const int lane = tid & 31;
  const int wid  = tid >> 5;
  const int g = lane >> 2, t = lane & 3;
  const int wm = wid >> 1;                 // 0..3 -> m offset 32*wm
  const int wn = wid & 1;                  // 0..1 -> n offset 64*wn
  const int row0 = blockIdx.y * MBM;
  const int col0 = blockIdx.x * MBN;

  unsigned smbase;
  { unsigned long long p = __cvta_generic_to_shared(smu); smbase = (unsigned)p; }

  // stage layout (word offsets): Ah[0], Al[MBM*ASTR], Bh[2*MBM*ASTR], Bl[.. + MBK*BSTR]
  const int AhO = 0, AlO = MBM * ASTR, BhO = 2 * MBM * ASTR, BlO = 2 * MBM * ASTR + MBK * BSTR;

  auto load_stage = [&](int s, int k0) {
    unsigned base = smbase + (unsigned)(s * STAGE_WORDS) * 4u;
#pragma unroll
    for (int i = 0; i < 4; i++) {
      int idx = tid + i * 256;           // 0..1023
      int m = idx >> 3, q = idx & 7;     // row, k-quad
      size_t src = (size_t)(row0 + m) * XSTRIDE + k0 + 4 * q;
      unsigned dst = (unsigned)(m * ASTR + 4 * q) * 4u;
      cpasync16(base + (AhO * 4u) + dst, &g_Xhi[src]);
      cpasync16(base + (AlO * 4u) + dst, &g_Xlo[src]);
    }
#pragma unroll
    for (int i = 0; i < 4; i++) {
      int idx = tid + i * 256;           // 0..1023
      int kk = idx >> 5, q = idx & 31;   // k-row, n-quad
      size_t src = (size_t)(k0 + kk) * 384 + col0 + 4 * q;
      unsigned dst = (unsigned)(kk * BSTR + 4 * q) * 4u;
      cpasync16(base + (BhO * 4u) + dst, &g_Whi[src]);
      cpasync16(base + (BlO * 4u) + dst, &g_Wlo[src]);
    }
  };

  float acc[2][8][4];
#pragma unroll
  for (int i = 0; i < 2; i++)
#pragma unroll
    for (int j = 0; j < 8; j++)
#pragma unroll
      for (int r = 0; r < 4; r++) acc[i][j][r] = 0.f;

  const int NIT = XSTRIDE / MBK;   // 76
  load_stage(0, 0);
  cp_commit();

  for (int it = 0; it < NIT; it++) {
    if (it + 1 < NIT) {
      load_stage((it + 1) & 1, (it + 1) * MBK);
      cp_commit();
      cp_wait<1>();
    } else {
      cp_wait<0>();
    }
    __syncthreads();

    const unsigned* Ah = smu + (it & 1) * STAGE_WORDS + AhO;
    const unsigned* Al = smu + (it & 1) * STAGE_WORDS + AlO;
    const unsigned* Bh = smu + (it & 1) * STAGE_WORDS + BhO;
    const unsigned* Bl = smu + (it & 1) * STAGE_WORDS + BlO;

#pragma unroll
    for (int ks = 0; ks < MBK / 8; ks++) {
      int k8 = ks * 8;
      unsigned ah[2][4], al[2][4];
#pragma unroll
      for (int mf = 0; mf < 2; mf++) {
        int r0i = (wm * 32 + mf * 16 + g) * ASTR + k8 + t;
        int r1i = r0i + 8 * ASTR;
        ah[mf][0] = Ah[r0i];     ah[mf][1] = Ah[r1i];
        ah[mf][2] = Ah[r0i + 4]; ah[mf][3] = Ah[r1i + 4];
        al[mf][0] = Al[r0i];     al[mf][1] = Al[r1i];
        al[mf][2] = Al[r0i + 4]; al[mf][3] = Al[r1i + 4];
      }
#pragma unroll
      for (int nf = 0; nf < 8; nf++) {
        int c0i = (k8 + t) * BSTR + wn * 64 + nf * 8 + g;
        unsigned bh0 = Bh[c0i], bh1 = Bh[c0i + 4 * BSTR];
        unsigned bl0 = Bl[c0i], bl1 = Bl[c0i + 4 * BSTR];
#pragma unroll
        for (int mf = 0; mf < 2; mf++) {
          float* d = acc[mf][nf];
          mma_tf32(d[0], d[1], d[2], d[3],
                   ah[mf][0], ah[mf][1], ah[mf][2], ah[mf][3], bh0, bh1);
          mma_tf32(d[0], d[1], d[2], d[3],
                   ah[mf][0], ah[mf][1], ah[mf][2], ah[mf][3], bl0, bl1);
          mma_tf32(d[0], d[1], d[2], d[3],
                   al[mf][0], al[mf][1], al[mf][2], al[mf][3], bh0, bh1);
        }
      }
    }
    __syncthreads();
  }

  // --- epilogue: bias + exact GELU -> g_H ---
#pragma unroll
  for (int mf = 0; mf < 2; mf++) {
    int r0 = row0 + wm * 32 + mf * 16 + g;
#pragma unroll
    for (int nf = 0; nf < 8; nf++) {
      int c0 = col0 + wn * 64 + nf * 8 + 2 * t;
      float b0 = bias[c0], b1 = bias[c0 + 1];
      const float* d = acc[mf][nf];
      float v;
      v = d[0] + b0; g_H[(size_t)r0 * 384 + c0]           = 0.5f * v * (1.f + erff(v * 0.70710678118654752f));
      v = d[1] + b1; g_H[(size_t)r0 * 384 + c0 + 1]       = 0.5f * v * (1.f + erff(v * 0.70710678118654752f));
      v = d[2] + b0; g_H[(size_t)(r0 + 8) * 384 + c0]     = 0.5f * v * (1.f + erff(v * 0.70710678118654752f));
      v = d[3] + b1; g_H[(size_t)(r0 + 8) * 384 + c0 + 1] = 0.5f * v * (1.f + erff(v * 0.70710678118654752f));
    }
  }
}

// ============================================================
// Kernel 3: out = H @ w2 + b2, scattered into concat layout (fp32 FFMA)
// ============================================================
#define BM 128
#define BN 64
#define BK 16

__global__ __launch_bounds__(256) void k_mlp2(const float* __restrict__ Bw,
                                              const float* __restrict__ bias,
                                              float* __restrict__ out) {
  __shared__ float As[BK][BM + 4];
  __shared__ float Bs[BK][BN];
  const int K = 384, Nn = 256;
  int tid = threadIdx.x;
  int tx = tid & 15, ty = tid >> 4;
  int col0 = blockIdx.x * BN;
  int row0 = blockIdx.y * BM;

  float acc[8][4];
#pragma unroll
  for (int i = 0; i < 8; i++)
#pragma unroll
    for (int j = 0; j < 4; j++) acc[i][j] = 0.f;

  for (int k0 = 0; k0 < K; k0 += BK) {
#pragma unroll
    for (int i = 0; i < 8; i++) {
      int idx = tid + i * 256;
      int m = idx >> 4, kk = idx & 15;
      As[kk][m] = g_H[(size_t)(row0 + m) * K + k0 + kk];
    }
#pragma unroll
    for (int i = 0; i < 4; i++) {
      int idx = tid + i * 256;
      int kk = idx >> 6, j = idx & 63;
      Bs[kk][j] = Bw[(size_t)(k0 + kk) * Nn + col0 + j];
    }
    __syncthreads();
#pragma unroll
    for (int kk = 0; kk < BK; kk++) {
      float4 a0 = *(const float4*)&As[kk][ty * 8];
      float4 a1 = *(const float4*)&As[kk][ty * 8 + 4];
      float4 b0 = *(const float4*)&Bs[kk][tx * 4];
      float a[8] = {a0.x, a0.y, a0.z, a0.w, a1.x, a1.y, a1.z, a1.w};
      float b[4] = {b0.x, b0.y, b0.z, b0.w};
#pragma unroll
      for (int i = 0; i < 8; i++)
#pragma unroll
        for (int j = 0; j < 4; j++) acc[i][j] += a[i] * b[j];
    }
    __syncthreads();
  }

#pragma unroll
  for (int i = 0; i < 8; i++)
#pragma unroll
    for (int j = 0; j < 4; j++) {
      int m = row0 + ty * 8 + i;
      int lev = m >> 12;
      int npt = m & 4095;
      int jg = col0 + tx * 4 + j;
      out[(size_t)npt * 1024 + lev * 256 + jg] = acc[i][j] + bias[jg];
    }
}

// ============================================================
// Launch
// ============================================================
extern "C" void kernel_launch(void* const* d_in, const int* in_sizes, int n_in,
                              void* d_out, int out_size) {
  const float* fm[4] = {0, 0, 0, 0};
  const float* tf[4] = {0, 0, 0, 0};
  const float* coords = 0;
  const float* w1 = 0; const float* b1 = 0;
  const float* w2 = 0; const float* b2 = 0;
  int tfi = 0, seen98304 = 0;
  for (int i = 0; i < n_in; i++) {
    const float* p = (const float*)d_in[i];
    switch (in_sizes[i]) {
      case 1572864:  fm[0] = p; break;
      case 393216:   fm[1] = p; break;
      case 98304:    if (!seen98304) { fm[2] = p; seen98304 = 1; } else w2 = p; break;
      case 24576:    fm[3] = p; break;
      case 25690112: if (tfi < 4) tf[tfi++] = p; break;
      case 8192:     coords = p; break;
      case 921984:   w1 = p; break;
      case 384:      b1 = p; break;
      case 256:      b2 = p; break;
      default: break;
    }
  }

  static const int Hs[4]   = {96, 48, 24, 12};
  static const int Ws[4]   = {128, 64, 32, 16};
  static const int offs[4] = {0, 1572864, 1966080, 2064384};

  for (int l = 0; l < 4; l++)
    k_transpose<<<Hs[l] * Ws[l], 128>>>(fm[l], Hs[l] * Ws[l], offs[l]);

  k_wsplit<<<(2401 * 384 + 255) / 256, 256>>>(w1);

  const int corrSmem = 2 * GG * PAD * 4;  // 51744 B
  cudaFuncSetAttribute(k_corr, cudaFuncAttributeMaxDynamicSharedMemorySize, corrSmem);
  for (int l = 0; l < 4; l++) {
    float scale = 1.f / (float)(1 << l);
    k_corr<<<NPTS, 256, corrSmem>>>(tf[l], coords, Hs[l], Ws[l], offs[l], l, scale);
  }

  const int mlp1Smem = 2 * STAGE_WORDS * 4;  // 143360 B
  cudaFuncSetAttribute(k_mlp1, cudaFuncAttributeMaxDynamicSharedMemorySize, mlp1Smem);
  k_mlp1<<<dim3(384 / MBN, MROWS / MBM), 256, mlp1Smem>>>(b1);

  k_mlp2<<<dim3(256 / BN, MROWS / BM), 256>>>(w2, b2, (float*)d_out);
}